// round 3
// baseline (speedup 1.0000x reference)
#include <cuda_runtime.h>
#include <math.h>

#define T_TOK  16384
#define DMODEL 512
#define NEXP   8
#define NPRIM  16
#define RNK    64
#define KR     256     /* TOP_K_PRIM * RANK */
#define DFF    2048

// ---------------- static scratch (no dynamic allocation allowed) ----------------
__device__ float d_U[(size_t)NEXP * T_TOK * KR];      // 128 MB
__device__ float d_H[(size_t)NEXP * T_TOK * DFF];     // 1 GB
__device__ float d_V[(size_t)NEXP * T_TOK * KR];      // 128 MB
__device__ float d_A1c[NEXP * DMODEL * KR];           // 4 MB
__device__ float d_B1c[NEXP * KR * DFF];              // 16 MB
__device__ float d_A2c[NEXP * DFF * KR];              // 16 MB
__device__ float d_B2c[NEXP * KR * DMODEL];           // 4 MB
__device__ int   d_cnt[NEXP];
__device__ int   d_gtok[NEXP * T_TOK];
__device__ float d_ggate[NEXP * T_TOK];
__device__ float d_Ppart[64 * NEXP];
__device__ float d_sw1[NEXP * 4];
__device__ int   d_si1[NEXP * 4];
__device__ float d_sw2[NEXP * 4];
__device__ int   d_si2[NEXP * 4];

__device__ __forceinline__ float gelu_exact(float v) {
    return 0.5f * v * (1.0f + erff(v * 0.70710678118654752f));
}

// ---------------- zero init ----------------
__global__ void zero_kernel(float* out, long long n) {
    long long i = (long long)blockIdx.x * blockDim.x + threadIdx.x;
    long long stride = (long long)gridDim.x * blockDim.x;
    for (long long j = i; j < n; j += stride) out[j] = 0.0f;
    if (i < NEXP) d_cnt[i] = 0;
    if (i < 64 * NEXP) d_Ppart[i] = 0.0f;
}

// ---------------- router: one warp per token ----------------
__global__ void router_kernel(const float* __restrict__ x, const float* __restrict__ Wr) {
    const int warp = threadIdx.x >> 5;
    const int lane = threadIdx.x & 31;
    const int t = blockIdx.x * 8 + warp;

    float part[NEXP];
#pragma unroll
    for (int e = 0; e < NEXP; e++) part[e] = 0.0f;

    const float* xr = x + (size_t)t * DMODEL;
    for (int i = lane; i < DMODEL; i += 32) {
        float xv = xr[i];
#pragma unroll
        for (int e = 0; e < NEXP; e++) part[e] += xv * Wr[e * DMODEL + i];
    }
#pragma unroll
    for (int e = 0; e < NEXP; e++) {
#pragma unroll
        for (int off = 16; off > 0; off >>= 1)
            part[e] += __shfl_xor_sync(0xffffffffu, part[e], off);
    }

    __shared__ float sP[8][NEXP];
    __shared__ int   sE[8][2];
    __shared__ float sW[8][2];

    if (lane == 0) {
        float mx = part[0];
#pragma unroll
        for (int e = 1; e < NEXP; e++) mx = fmaxf(mx, part[e]);
        float p[NEXP], s = 0.0f;
#pragma unroll
        for (int e = 0; e < NEXP; e++) { p[e] = expf(part[e] - mx); s += p[e]; }
#pragma unroll
        for (int e = 0; e < NEXP; e++) { p[e] /= s; sP[warp][e] = p[e]; }
        // top-2
        int e0 = 0;
#pragma unroll
        for (int e = 1; e < NEXP; e++) if (p[e] > p[e0]) e0 = e;
        int e1 = (e0 == 0) ? 1 : 0;
#pragma unroll
        for (int e = 0; e < NEXP; e++) if (e != e0 && p[e] > p[e1]) e1 = e;
        float s2 = p[e0] + p[e1] + 1e-8f;
        sE[warp][0] = e0; sE[warp][1] = e1;
        sW[warp][0] = p[e0] / s2; sW[warp][1] = p[e1] / s2;
    }
    __syncthreads();

    int tid = threadIdx.x;
    if (tid < NEXP) {
        float s = 0.0f;
#pragma unroll
        for (int w = 0; w < 8; w++) s += sP[w][tid];
        atomicAdd(&d_Ppart[(blockIdx.x & 63) * NEXP + tid], s);

        int cnt = 0;
#pragma unroll
        for (int w = 0; w < 8; w++)
#pragma unroll
            for (int k = 0; k < 2; k++)
                if (sE[w][k] == tid) cnt++;
        if (cnt) {
            int base = atomicAdd(&d_cnt[tid], cnt);
#pragma unroll
            for (int w = 0; w < 8; w++)
#pragma unroll
                for (int k = 0; k < 2; k++)
                    if (sE[w][k] == tid) {
                        d_gtok[tid * T_TOK + base]  = blockIdx.x * 8 + w;
                        d_ggate[tid * T_TOK + base] = sW[w][k];
                        base++;
                    }
        }
    }
}

// ---------------- primitive composition (top-4 of 16, sqrt weights) ----------------
__global__ void compose_kernel(const float* __restrict__ fc1, const float* __restrict__ fc2) {
    int tid = threadIdx.x;
    if (tid >= 16) return;
    int l = tid >> 3, e = tid & 7;
    const float* lg = (l ? fc2 : fc1) + e * NPRIM;
    float p[NPRIM];
    float mx = lg[0];
    for (int i = 1; i < NPRIM; i++) mx = fmaxf(mx, lg[i]);
    float s = 0.0f;
    for (int i = 0; i < NPRIM; i++) { p[i] = expf(lg[i] - mx); s += p[i]; }
    for (int i = 0; i < NPRIM; i++) p[i] /= s;

    bool taken[NPRIM];
    for (int i = 0; i < NPRIM; i++) taken[i] = false;
    int   idx[4];
    float tw[4];
    for (int k = 0; k < 4; k++) {
        int best = -1;
        for (int i = 0; i < NPRIM; i++)
            if (!taken[i] && (best < 0 || p[i] > p[best])) best = i;
        taken[best] = true;
        idx[k] = best;
        tw[k]  = p[best];
    }
    float s4 = tw[0] + tw[1] + tw[2] + tw[3] + 1e-8f;
    float* sw = l ? d_sw2 : d_sw1;
    int*   si = l ? d_si2 : d_si1;
    for (int k = 0; k < 4; k++) {
        sw[e * 4 + k] = sqrtf(tw[k] / s4 + 1e-8f);
        si[e * 4 + k] = idx[k];
    }
}

// ---------------- materialize composed weights ----------------
// A-type: src (P, X, RNK) -> dst (E, X, KR): dst[e][x][k*64+r] = w * src[p][x][r]
__global__ void matA_kernel(const float* __restrict__ src, int which) {
    float* dst      = which ? d_A2c : d_A1c;
    int X           = which ? DFF : DMODEL;
    const float* sw = which ? d_sw2 : d_sw1;
    const int*   si = which ? d_si2 : d_si1;
    int total = NEXP * X * KR;
    int i = blockIdx.x * blockDim.x + threadIdx.x;
    if (i >= total) return;
    int c = i % KR;
    int rem = i / KR;
    int xi = rem % X;
    int e  = rem / X;
    int k = c >> 6, r = c & 63;
    int p = si[e * 4 + k];
    dst[i] = sw[e * 4 + k] * src[((size_t)p * X + xi) * RNK + r];
}

// B-type: src (P, RNK, F) -> dst (E, KR, F): dst[e][k*64+r][f] = w * src[p][r][f]
__global__ void matB_kernel(const float* __restrict__ src, int which) {
    float* dst      = which ? d_B2c : d_B1c;
    int F           = which ? DMODEL : DFF;
    const float* sw = which ? d_sw2 : d_sw1;
    const int*   si = which ? d_si2 : d_si1;
    int total = NEXP * KR * F;
    int i = blockIdx.x * blockDim.x + threadIdx.x;
    if (i >= total) return;
    int f = i % F;
    int rem = i / F;
    int c = rem % KR;
    int e = rem / KR;
    int k = c >> 6, r = c & 63;
    int p = si[e * 4 + k];
    dst[i] = sw[e * 4 + k] * src[((size_t)p * RNK + r) * F + f];
}

// ---------------- tiled fp32 GEMM, stage-specialized ----------------
// STAGE 1: U[m,256] = gather(x)[m,512] @ A1c          (GATHER)
// STAGE 2: H[m,2048] = gelu(U[m,256] @ B1c)           (GELU)
// STAGE 3: V[m,256] = H[m,2048] @ A2c
// STAGE 4: out[tok,512] += gate * (V[m,256] @ B2c)    (SCATTER atomicAdd)
template <int STAGE>
__global__ __launch_bounds__(256) void gemm_stage(const float* __restrict__ xin,
                                                  float* __restrict__ outp) {
    constexpr int K = (STAGE == 1) ? DMODEL : (STAGE == 3) ? DFF : KR;
    constexpr int N = (STAGE == 2) ? DFF : (STAGE == 4) ? DMODEL : KR;
    constexpr bool GATHER  = (STAGE == 1);
    constexpr bool GELU    = (STAGE == 2);
    constexpr bool SCATTER = (STAGE == 4);

    const int e = blockIdx.z;
    const int cnt = d_cnt[e];
    const int m0 = blockIdx.x * 128;
    if (m0 >= cnt) return;
    const int n0 = blockIdx.y * 128;

    const float* A;
    const float* B;
    float* C;
    if (STAGE == 1) { A = xin;                            B = d_A1c + (size_t)e * DMODEL * KR; C = d_U + (size_t)e * T_TOK * KR;  }
    if (STAGE == 2) { A = d_U + (size_t)e * T_TOK * KR;   B = d_B1c + (size_t)e * KR * DFF;    C = d_H + (size_t)e * T_TOK * DFF; }
    if (STAGE == 3) { A = d_H + (size_t)e * T_TOK * DFF;  B = d_A2c + (size_t)e * DFF * KR;    C = d_V + (size_t)e * T_TOK * KR;  }
    if (STAGE == 4) { A = d_V + (size_t)e * T_TOK * KR;   B = d_B2c + (size_t)e * KR * DMODEL; C = outp;                          }

    const int* tokp  = d_gtok  + e * T_TOK;
    const float* gtp = d_ggate + e * T_TOK;

    __shared__ float As[8][128];
    __shared__ float Bs[8][128];

    const int tid  = threadIdx.x;
    const int arow = tid >> 1;
    const int acol = (tid & 1) * 4;
    const int brow = tid >> 5;
    const int bcol = (tid & 31) * 4;
    const int ty = tid >> 4;
    const int tx = tid & 15;

    // per-thread A row base pointer
    const int am = m0 + arow;
    const bool avalid = (am < cnt);
    const float* arowp = nullptr;
    if (avalid) {
        if (GATHER) arowp = A + (size_t)tokp[am] * K;
        else        arowp = A + (size_t)am * K;
    }

    float acc[8][8];
#pragma unroll
    for (int i = 0; i < 8; i++)
#pragma unroll
        for (int j = 0; j < 8; j++) acc[i][j] = 0.0f;

    for (int k0 = 0; k0 < K; k0 += 8) {
        float4 av = make_float4(0.f, 0.f, 0.f, 0.f);
        if (avalid) av = *(const float4*)(arowp + k0 + acol);
        As[acol + 0][arow] = av.x;
        As[acol + 1][arow] = av.y;
        As[acol + 2][arow] = av.z;
        As[acol + 3][arow] = av.w;

        float4 bv = *(const float4*)(B + (size_t)(k0 + brow) * N + n0 + bcol);
        *(float4*)&Bs[brow][bcol] = bv;

        __syncthreads();

#pragma unroll
        for (int kk = 0; kk < 8; kk++) {
            float4 a0 = *(const float4*)&As[kk][ty * 8];
            float4 a1 = *(const float4*)&As[kk][ty * 8 + 4];
            float4 b0 = *(const float4*)&Bs[kk][tx * 8];
            float4 b1 = *(const float4*)&Bs[kk][tx * 8 + 4];
            float ar[8] = {a0.x, a0.y, a0.z, a0.w, a1.x, a1.y, a1.z, a1.w};
            float br[8] = {b0.x, b0.y, b0.z, b0.w, b1.x, b1.y, b1.z, b1.w};
#pragma unroll
            for (int i = 0; i < 8; i++)
#pragma unroll
                for (int j = 0; j < 8; j++)
                    acc[i][j] += ar[i] * br[j];
        }
        __syncthreads();
    }

#pragma unroll
    for (int i = 0; i < 8; i++) {
        int m = m0 + ty * 8 + i;
        if (m >= cnt) continue;
        if (SCATTER) {
            int t  = tokp[m];
            float g = gtp[m];
            float* orow = C + (size_t)t * N + n0 + tx * 8;
#pragma unroll
            for (int j = 0; j < 8; j++) atomicAdd(&orow[j], g * acc[i][j]);
        } else {
            float* crow = C + (size_t)m * N + n0 + tx * 8;
#pragma unroll
            for (int j = 0; j < 8; j++) {
                float v = acc[i][j];
                if (GELU) v = gelu_exact(v);
                crow[j] = v;
            }
        }
    }
}

// ---------------- aux loss ----------------
__global__ void aux_kernel(float* dst) {
    float aux = 0.0f;
    for (int e = 0; e < NEXP; e++) {
        float Ps = 0.0f;
        for (int j = 0; j < 64; j++) Ps += d_Ppart[j * NEXP + e];
        float f = (float)d_cnt[e] / (2.0f * T_TOK + 1e-8f);
        aux += f * (Ps / (float)T_TOK);
    }
    dst[0] = (float)NEXP * aux;
}

// ---------------- launch ----------------
extern "C" void kernel_launch(void* const* d_in, const int* in_sizes, int n_in,
                              void* d_out, int out_size) {
    const float* x   = (const float*)d_in[0];
    const float* Wr  = (const float*)d_in[1];
    const float* fc1 = (const float*)d_in[2];
    const float* fc2 = (const float*)d_in[3];
    const float* A1  = (const float*)d_in[4];
    const float* B1  = (const float*)d_in[5];
    const float* A2  = (const float*)d_in[6];
    const float* B2  = (const float*)d_in[7];
    float* out = (float*)d_out;

    const long long outN = (long long)T_TOK * DMODEL;

    zero_kernel<<<4096, 256>>>(out, (long long)out_size);
    router_kernel<<<T_TOK / 8, 256>>>(x, Wr);
    compose_kernel<<<1, 32>>>(fc1, fc2);
    matA_kernel<<<(NEXP * DMODEL * KR + 255) / 256, 256>>>(A1, 0);
    matB_kernel<<<(NEXP * KR * DFF + 255) / 256, 256>>>(B1, 0);
    matA_kernel<<<(NEXP * DFF * KR + 255) / 256, 256>>>(A2, 1);
    matB_kernel<<<(NEXP * KR * DMODEL + 255) / 256, 256>>>(B2, 1);

    gemm_stage<1><<<dim3(T_TOK / 128, KR / 128, NEXP), 256>>>(x, nullptr);
    gemm_stage<2><<<dim3(T_TOK / 128, DFF / 128, NEXP), 256>>>(nullptr, nullptr);
    gemm_stage<3><<<dim3(T_TOK / 128, KR / 128, NEXP), 256>>>(nullptr, nullptr);
    gemm_stage<4><<<dim3(T_TOK / 128, DMODEL / 128, NEXP), 256>>>(nullptr, out);

    if ((long long)out_size > outN) {
        aux_kernel<<<1, 1>>>(out + outN);
    }
}

// round 15
// speedup vs baseline: 1.1106x; 1.1106x over previous
#include <cuda_runtime.h>
#include <cuda_bf16.h>
#include <mma.h>
#include <math.h>
#include <stdint.h>

using namespace nvcuda;

#define T_TOK  16384
#define DMODEL 512
#define NEXP   8
#define NPRIM  16
#define RNK    64
#define KR     256
#define DFF    2048

// ---------------- static scratch (vector-typed for guaranteed 16B alignment) ---
__device__ float4 d_U4[(size_t)NEXP * T_TOK * KR / 4];     // 128 MB
__device__ float4 d_H4[(size_t)NEXP * T_TOK * DFF / 4];    // 1 GB
__device__ float4 d_V4[(size_t)NEXP * T_TOK * KR / 4];     // 128 MB
__device__ float  d_A1c[NEXP * DMODEL * KR];               // 4 MB
__device__ float  d_A2c[NEXP * DFF * KR];                  // 16 MB
__device__ float  d_B2c[NEXP * KR * DMODEL];               // 4 MB
// stage-2 weights: bf16 hi/lo, transposed [e][n=DFF][k=KR], stored as uint4
__device__ uint4  d_W2h4[(size_t)NEXP * DFF * KR * 2 / 16];  // 8 MB
__device__ uint4  d_W2l4[(size_t)NEXP * DFF * KR * 2 / 16];  // 8 MB
__device__ int    d_cnt[NEXP];
__device__ int    d_gtok[NEXP * T_TOK];
__device__ float  d_ggate[NEXP * T_TOK];
__device__ float  d_Ppart[64 * NEXP];
__device__ float  d_sw1[NEXP * 4];
__device__ int    d_si1[NEXP * 4];
__device__ float  d_sw2[NEXP * 4];
__device__ int    d_si2[NEXP * 4];

__device__ __forceinline__ float gelu_exact(float v) {
    return 0.5f * v * (1.0f + erff(v * 0.70710678118654752f));
}
__device__ __forceinline__ void split_bf16(float v, __nv_bfloat16& h, __nv_bfloat16& l) {
    h = __float2bfloat16_rn(v);
    l = __float2bfloat16_rn(v - __bfloat162float(h));
}

// ---------------- zero init ----------------
__global__ void zero_kernel(float* out, long long n) {
    long long i = (long long)blockIdx.x * blockDim.x + threadIdx.x;
    long long stride = (long long)gridDim.x * blockDim.x;
    for (long long j = i; j < n; j += stride) out[j] = 0.0f;
    if (i < NEXP) d_cnt[i] = 0;
    if (i < 64 * NEXP) d_Ppart[i] = 0.0f;
}

// ---------------- router: one warp per token (round-1 verbatim) ----------------
__global__ void router_kernel(const float* __restrict__ x, const float* __restrict__ Wr) {
    const int warp = threadIdx.x >> 5;
    const int lane = threadIdx.x & 31;
    const int t = blockIdx.x * 8 + warp;

    float part[NEXP];
#pragma unroll
    for (int e = 0; e < NEXP; e++) part[e] = 0.0f;
    const float* xr = x + (size_t)t * DMODEL;
    for (int i = lane; i < DMODEL; i += 32) {
        float xv = xr[i];
#pragma unroll
        for (int e = 0; e < NEXP; e++) part[e] += xv * Wr[e * DMODEL + i];
    }
#pragma unroll
    for (int e = 0; e < NEXP; e++) {
#pragma unroll
        for (int off = 16; off > 0; off >>= 1)
            part[e] += __shfl_xor_sync(0xffffffffu, part[e], off);
    }

    __shared__ float sP[8][NEXP];
    __shared__ int   sE[8][2];
    __shared__ float sW[8][2];

    if (lane == 0) {
        float mx = part[0];
#pragma unroll
        for (int e = 1; e < NEXP; e++) mx = fmaxf(mx, part[e]);
        float p[NEXP], s = 0.0f;
#pragma unroll
        for (int e = 0; e < NEXP; e++) { p[e] = expf(part[e] - mx); s += p[e]; }
#pragma unroll
        for (int e = 0; e < NEXP; e++) { p[e] /= s; sP[warp][e] = p[e]; }
        int e0 = 0;
#pragma unroll
        for (int e = 1; e < NEXP; e++) if (p[e] > p[e0]) e0 = e;
        int e1 = (e0 == 0) ? 1 : 0;
#pragma unroll
        for (int e = 0; e < NEXP; e++) if (e != e0 && p[e] > p[e1]) e1 = e;
        float s2 = p[e0] + p[e1] + 1e-8f;
        sE[warp][0] = e0; sE[warp][1] = e1;
        sW[warp][0] = p[e0] / s2; sW[warp][1] = p[e1] / s2;
    }
    __syncthreads();

    int tid = threadIdx.x;
    if (tid < NEXP) {
        float s = 0.0f;
#pragma unroll
        for (int w = 0; w < 8; w++) s += sP[w][tid];
        atomicAdd(&d_Ppart[(blockIdx.x & 63) * NEXP + tid], s);

        int cnt = 0;
#pragma unroll
        for (int w = 0; w < 8; w++)
#pragma unroll
            for (int k = 0; k < 2; k++)
                if (sE[w][k] == tid) cnt++;
        if (cnt) {
            int base = atomicAdd(&d_cnt[tid], cnt);
#pragma unroll
            for (int w = 0; w < 8; w++)
#pragma unroll
                for (int k = 0; k < 2; k++)
                    if (sE[w][k] == tid) {
                        d_gtok[tid * T_TOK + base]  = blockIdx.x * 8 + w;
                        d_ggate[tid * T_TOK + base] = sW[w][k];
                        base++;
                    }
        }
    }
}

// ---------------- primitive composition (round-1 verbatim) ----------------
__global__ void compose_kernel(const float* __restrict__ fc1, const float* __restrict__ fc2) {
    int tid = threadIdx.x;
    if (tid >= 16) return;
    int l = tid >> 3, e = tid & 7;
    const float* lg = (l ? fc2 : fc1) + e * NPRIM;
    float p[NPRIM];
    float mx = lg[0];
    for (int i = 1; i < NPRIM; i++) mx = fmaxf(mx, lg[i]);
    float s = 0.0f;
    for (int i = 0; i < NPRIM; i++) { p[i] = expf(lg[i] - mx); s += p[i]; }
    for (int i = 0; i < NPRIM; i++) p[i] /= s;

    bool taken[NPRIM];
    for (int i = 0; i < NPRIM; i++) taken[i] = false;
    int idx[4]; float tw[4];
    for (int k = 0; k < 4; k++) {
        int best = -1;
        for (int i = 0; i < NPRIM; i++)
            if (!taken[i] && (best < 0 || p[i] > p[best])) best = i;
        taken[best] = true; idx[k] = best; tw[k] = p[best];
    }
    float s4 = tw[0] + tw[1] + tw[2] + tw[3] + 1e-8f;
    float* sw = l ? d_sw2 : d_sw1;
    int*   si = l ? d_si2 : d_si1;
    for (int k = 0; k < 4; k++) {
        sw[e * 4 + k] = sqrtf(tw[k] / s4 + 1e-8f);
        si[e * 4 + k] = idx[k];
    }
}

// ---------------- materialize fp32 composed weights (round-1 style) ----------------
// A-type: src (P, X, RNK) -> dst (E, X, KR)
__global__ void matA_kernel(const float* __restrict__ src, int which) {
    float* dst      = which ? d_A2c : d_A1c;
    int X           = which ? DFF : DMODEL;
    const float* sw = which ? d_sw2 : d_sw1;
    const int*   si = which ? d_si2 : d_si1;
    int total = NEXP * X * KR;
    int i = blockIdx.x * blockDim.x + threadIdx.x;
    if (i >= total) return;
    int c = i % KR;
    int rem = i / KR;
    int xi = rem % X;
    int e  = rem / X;
    int k = c >> 6, r = c & 63;
    int p = si[e * 4 + k];
    dst[i] = sw[e * 4 + k] * src[((size_t)p * X + xi) * RNK + r];
}

// B-type (fp32, stage 4): src (P, RNK, F) -> dst (E, KR, F)
__global__ void matB_kernel(const float* __restrict__ src) {
    const int F = DMODEL;
    int total = NEXP * KR * F;
    int i = blockIdx.x * blockDim.x + threadIdx.x;
    if (i >= total) return;
    int f = i % F;
    int rem = i / F;
    int c = rem % KR;
    int e = rem / KR;
    int k = c >> 6, r = c & 63;
    int p = d_si2[e * 4 + k];
    d_B2c[i] = d_sw2[e * 4 + k] * src[((size_t)p * RNK + r) * F + f];
}

// B1 transposed bf16 hi/lo for wmma stage 2: src B1 (P, RNK, DFF) ->
// dst [e][n=DFF][k=KR] = sw1 * src[p][k&63][n]
__global__ void matB1_T_kernel(const float* __restrict__ src) {
    __nv_bfloat16* hi = reinterpret_cast<__nv_bfloat16*>(d_W2h4);
    __nv_bfloat16* lo = reinterpret_cast<__nv_bfloat16*>(d_W2l4);
    int i = blockIdx.x * blockDim.x + threadIdx.x;
    int total = NEXP * DFF * KR;
    if (i >= total) return;
    int k = i % KR;
    int rem = i / KR;
    int n = rem % DFF;
    int e = rem / DFF;
    int kp = k >> 6, r = k & 63;
    int p = d_si1[e * 4 + kp];
    float v = d_sw1[e * 4 + kp] * src[((size_t)p * RNK + r) * DFF + n];
    split_bf16(v, hi[i], lo[i]);
}

// ---------------- SIMT fp32 GEMM (round-1 engine, stages 1/3/4) ----------------
// STAGE 1: U[m,256] = gather(x)[m,512] @ A1c          (GATHER)
// STAGE 3: V[m,256] = H[m,2048] @ A2c
// STAGE 4: out[tok,512] += gate * (V[m,256] @ B2c)    (SCATTER atomicAdd)
template <int STAGE>
__global__ __launch_bounds__(256) void gemm_stage(const float* __restrict__ xin,
                                                  float* __restrict__ outp) {
    constexpr int K = (STAGE == 1) ? DMODEL : (STAGE == 3) ? DFF : KR;
    constexpr int N = (STAGE == 4) ? DMODEL : KR;
    constexpr bool GATHER  = (STAGE == 1);
    constexpr bool SCATTER = (STAGE == 4);

    const int e = blockIdx.z;
    const int cnt = d_cnt[e];
    const int m0 = blockIdx.x * 128;
    if (m0 >= cnt) return;
    const int n0 = blockIdx.y * 128;

    const float* A;
    const float* B;
    float* C;
    if (STAGE == 1) { A = xin;
                      B = d_A1c + (size_t)e * DMODEL * KR;
                      C = reinterpret_cast<float*>(d_U4) + (size_t)e * T_TOK * KR; }
    if (STAGE == 3) { A = reinterpret_cast<const float*>(d_H4) + (size_t)e * T_TOK * DFF;
                      B = d_A2c + (size_t)e * DFF * KR;
                      C = reinterpret_cast<float*>(d_V4) + (size_t)e * T_TOK * KR; }
    if (STAGE == 4) { A = reinterpret_cast<const float*>(d_V4) + (size_t)e * T_TOK * KR;
                      B = d_B2c + (size_t)e * KR * DMODEL;
                      C = outp; }

    const int* tokp  = d_gtok  + e * T_TOK;
    const float* gtp = d_ggate + e * T_TOK;

    __shared__ float As[8][128];
    __shared__ float Bs[8][128];

    const int tid  = threadIdx.x;
    const int arow = tid >> 1;
    const int acol = (tid & 1) * 4;
    const int brow = tid >> 5;
    const int bcol = (tid & 31) * 4;
    const int ty = tid >> 4;
    const int tx = tid & 15;

    const int am = m0 + arow;
    const bool avalid = (am < cnt);
    const float* arowp = nullptr;
    if (avalid) {
        if (GATHER) arowp = A + (size_t)tokp[am] * K;
        else        arowp = A + (size_t)am * K;
    }

    float acc[8][8];
#pragma unroll
    for (int i = 0; i < 8; i++)
#pragma unroll
        for (int j = 0; j < 8; j++) acc[i][j] = 0.0f;

    for (int k0 = 0; k0 < K; k0 += 8) {
        float4 av = make_float4(0.f, 0.f, 0.f, 0.f);
        if (avalid) av = *(const float4*)(arowp + k0 + acol);
        As[acol + 0][arow] = av.x;
        As[acol + 1][arow] = av.y;
        As[acol + 2][arow] = av.z;
        As[acol + 3][arow] = av.w;

        float4 bv = *(const float4*)(B + (size_t)(k0 + brow) * N + n0 + bcol);
        *(float4*)&Bs[brow][bcol] = bv;

        __syncthreads();

#pragma unroll
        for (int kk = 0; kk < 8; kk++) {
            float4 a0 = *(const float4*)&As[kk][ty * 8];
            float4 a1 = *(const float4*)&As[kk][ty * 8 + 4];
            float4 b0 = *(const float4*)&Bs[kk][tx * 8];
            float4 b1 = *(const float4*)&Bs[kk][tx * 8 + 4];
            float ar[8] = {a0.x, a0.y, a0.z, a0.w, a1.x, a1.y, a1.z, a1.w};
            float br[8] = {b0.x, b0.y, b0.z, b0.w, b1.x, b1.y, b1.z, b1.w};
#pragma unroll
            for (int i = 0; i < 8; i++)
#pragma unroll
                for (int j = 0; j < 8; j++)
                    acc[i][j] += ar[i] * br[j];
        }
        __syncthreads();
    }

#pragma unroll
    for (int i = 0; i < 8; i++) {
        int m = m0 + ty * 8 + i;
        if (m >= cnt) continue;
        if (SCATTER) {
            int t  = tokp[m];
            float g = gtp[m];
            float* orow = C + (size_t)t * N + n0 + tx * 8;
#pragma unroll
            for (int j = 0; j < 8; j++) atomicAdd(&orow[j], g * acc[i][j]);
        } else {
            float* crow = C + (size_t)m * N + n0 + tx * 8;
#pragma unroll
            for (int j = 0; j < 8; j++) crow[j] = acc[i][j];
        }
    }
}

// ---------------- WMMA stage 2: H = gelu(U @ B1c), bf16 hi/lo compensated -------
// 128x128 CTA tile; 8 warps 2(m) x 4(n); warp tile 64x32; K=256 in chunks of 32.
#define KC      32
#define KS      40
#define TILEE   (128 * KS)

__global__ void __launch_bounds__(256) wmma_stage2() {
    constexpr int K  = KR;     // 256
    constexpr int Ng = DFF;    // 2048

    const int e = blockIdx.z;
    const int cnt = d_cnt[e];
    const int m0 = blockIdx.x * 128;
    if (m0 >= cnt) return;
    const int n0 = blockIdx.y * 128;

    __shared__ __align__(32) __nv_bfloat16 smem[4 * TILEE];
    __nv_bfloat16* sAh = smem;
    __nv_bfloat16* sAl = smem + TILEE;
    __nv_bfloat16* sBh = smem + 2 * TILEE;
    __nv_bfloat16* sBl = smem + 3 * TILEE;

    const int tid = threadIdx.x;

    const float* Af = reinterpret_cast<const float*>(d_U4) + (size_t)e * T_TOK * K;
    float*       Cf = reinterpret_cast<float*>(d_H4) + (size_t)e * T_TOK * Ng;
    const __nv_bfloat16* Bh = reinterpret_cast<const __nv_bfloat16*>(d_W2h4) + (size_t)e * Ng * K;
    const __nv_bfloat16* Bl = reinterpret_cast<const __nv_bfloat16*>(d_W2l4) + (size_t)e * Ng * K;

    // ---- A loader: row = tid>>1, 16 f32 at (tid&1)*16; clamp row to cnt-1 ----
    const int arow = tid >> 1;
    const int aoff = (tid & 1) * 16;
    int am = m0 + arow; if (am >= cnt) am = cnt - 1;
    const float* aptr = Af + (size_t)am * K + aoff;
    __nv_bfloat162* dAh = reinterpret_cast<__nv_bfloat162*>(sAh + arow * KS + aoff);
    __nv_bfloat162* dAl = reinterpret_cast<__nv_bfloat162*>(sAl + arow * KS + aoff);

    // ---- B loader: row = tid>>1, 16 bf16 at (tid&1)*16 ----
    const int brow = tid >> 1;
    const int bko  = (tid & 1) * 16;
    const __nv_bfloat16* pBh = Bh + (size_t)(n0 + brow) * K + bko;
    const __nv_bfloat16* pBl = Bl + (size_t)(n0 + brow) * K + bko;
    uint4* dBh = reinterpret_cast<uint4*>(sBh + brow * KS + bko);
    uint4* dBl = reinterpret_cast<uint4*>(sBl + brow * KS + bko);

    const int warp = tid >> 5;
    const int wm = warp & 1, wn = warp >> 1;

    wmma::fragment<wmma::accumulator, 16, 16, 16, float> c[4][2];
#pragma unroll
    for (int mi = 0; mi < 4; mi++)
#pragma unroll
        for (int nj = 0; nj < 2; nj++) wmma::fill_fragment(c[mi][nj], 0.0f);

    for (int ch = 0; ch < K / KC; ch++) {
        const int k0 = ch * KC;
        {
            const float4* s4 = reinterpret_cast<const float4*>(aptr + k0);
#pragma unroll
            for (int q = 0; q < 4; q++) {
                float4 v = s4[q];
                __nv_bfloat16 h0, l0, h1, l1, h2, l2, h3, l3;
                split_bf16(v.x, h0, l0); split_bf16(v.y, h1, l1);
                split_bf16(v.z, h2, l2); split_bf16(v.w, h3, l3);
                dAh[q * 2 + 0] = __nv_bfloat162(h0, h1);
                dAh[q * 2 + 1] = __nv_bfloat162(h2, h3);
                dAl[q * 2 + 0] = __nv_bfloat162(l0, l1);
                dAl[q * 2 + 1] = __nv_bfloat162(l2, l3);
            }
        }
        {
            const uint4* sh = reinterpret_cast<const uint4*>(pBh + k0);
            const uint4* sl = reinterpret_cast<const uint4*>(pBl + k0);
            dBh[0] = sh[0]; dBh[1] = sh[1];
            dBl[0] = sl[0]; dBl[1] = sl[1];
        }
        __syncthreads();

#pragma unroll
        for (int ks = 0; ks < 2; ks++) {
            wmma::fragment<wmma::matrix_b, 16, 16, 16, __nv_bfloat16, wmma::col_major> fbh[2], fbl[2];
#pragma unroll
            for (int nj = 0; nj < 2; nj++) {
                const int nb = wn * 32 + nj * 16;
                wmma::load_matrix_sync(fbh[nj], sBh + nb * KS + ks * 16, KS);
                wmma::load_matrix_sync(fbl[nj], sBl + nb * KS + ks * 16, KS);
            }
#pragma unroll
            for (int mi = 0; mi < 4; mi++) {
                const int mb = wm * 64 + mi * 16;
                wmma::fragment<wmma::matrix_a, 16, 16, 16, __nv_bfloat16, wmma::row_major> fah, fal;
                wmma::load_matrix_sync(fah, sAh + mb * KS + ks * 16, KS);
                wmma::load_matrix_sync(fal, sAl + mb * KS + ks * 16, KS);
#pragma unroll
                for (int nj = 0; nj < 2; nj++) {
                    wmma::mma_sync(c[mi][nj], fah, fbh[nj], c[mi][nj]);
                    wmma::mma_sync(c[mi][nj], fah, fbl[nj], c[mi][nj]);
                    wmma::mma_sync(c[mi][nj], fal, fbh[nj], c[mi][nj]);
                }
            }
        }
        __syncthreads();
    }

    // ---- epilogue: GELU on fragment, direct global store (rows >= cnt hold
    // clamped-row duplicates; never read downstream) ----
#pragma unroll
    for (int mi = 0; mi < 4; mi++) {
        const int mrow = m0 + wm * 64 + mi * 16;
#pragma unroll
        for (int nj = 0; nj < 2; nj++) {
            const int ncol = n0 + wn * 32 + nj * 16;
#pragma unroll
            for (int t = 0; t < c[mi][nj].num_elements; t++)
                c[mi][nj].x[t] = gelu_exact(c[mi][nj].x[t]);
            wmma::store_matrix_sync(Cf + (size_t)mrow * Ng + ncol, c[mi][nj], Ng,
                                    wmma::mem_row_major);
        }
    }
}

// ---------------- aux loss ----------------
__global__ void aux_kernel(float* dst) {
    float aux = 0.0f;
    for (int e = 0; e < NEXP; e++) {
        float Ps = 0.0f;
        for (int j = 0; j < 64; j++) Ps += d_Ppart[j * NEXP + e];
        float f = (float)d_cnt[e] / (2.0f * T_TOK + 1e-8f);
        aux += f * (Ps / (float)T_TOK);
    }
    dst[0] = (float)NEXP * aux;
}

// ---------------- launch ----------------
extern "C" void kernel_launch(void* const* d_in, const int* in_sizes, int n_in,
                              void* d_out, int out_size) {
    const float* x   = (const float*)d_in[0];
    const float* Wr  = (const float*)d_in[1];
    const float* fc1 = (const float*)d_in[2];
    const float* fc2 = (const float*)d_in[3];
    const float* A1  = (const float*)d_in[4];
    const float* B1  = (const float*)d_in[5];
    const float* A2  = (const float*)d_in[6];
    const float* B2  = (const float*)d_in[7];
    float* out = (float*)d_out;

    const long long outN = (long long)T_TOK * DMODEL;

    zero_kernel<<<4096, 256>>>(out, (long long)out_size);
    router_kernel<<<T_TOK / 8, 256>>>(x, Wr);
    compose_kernel<<<1, 32>>>(fc1, fc2);

    matA_kernel<<<(NEXP * DMODEL * KR + 255) / 256, 256>>>(A1, 0);
    matA_kernel<<<(NEXP * DFF * KR + 255) / 256, 256>>>(A2, 1);
    matB_kernel<<<(NEXP * KR * DMODEL + 255) / 256, 256>>>(B2);
    matB1_T_kernel<<<(NEXP * DFF * KR + 255) / 256, 256>>>(B1);

    gemm_stage<1><<<dim3(T_TOK / 128, KR / 128, NEXP), 256>>>(x, nullptr);
    wmma_stage2<<<dim3(T_TOK / 128, DFF / 128, NEXP), 256>>>();
    gemm_stage<3><<<dim3(T_TOK / 128, KR / 128, NEXP), 256>>>(nullptr, nullptr);
    gemm_stage<4><<<dim3(T_TOK / 128, DMODEL / 128, NEXP), 256>>>(nullptr, out);

    if ((long long)out_size > outN) {
        aux_kernel<<<1, 1>>>(out + outN);
    }
}